// round 16
// baseline (speedup 1.0000x reference)
#include <cuda_runtime.h>

// SelfAttention_61804579389661 — GB300 sm_103a — FINAL (converged)
// Best-of-session source, verified across 4 independent bench runs:
//   bench 43.49/43.52/43.52/43.74us; ncu kernel 42.62-44.00us,
//   HBM 6194-6390 GB/s (run-to-run DVFS noise); rel_err 2.05e-7 every run.
//
// Algebraic simplification: softmax over a size-1 axis is identically 1.0,
// so attention == 1 and context[b,u] = sum_s hidden_states[b,s,u]. The
// entire tanh/GEMM pipeline in the reference is dead code; the problem is a
// pure 256 MiB read-reduce, bandwidth-bound (floor ~42.2us at the ~6.35
// TB/s empirical streaming cap; this kernel sits at ~99% of it).
//
// Fully-explored design grid (R1-R15), evidence per axis:
//  - decomposition: strided U-chunk (6.33-6.39 TB/s) > contiguous-per-block
//    (5.98-6.0 TB/s), at both high and low occupancy;
//  - fusion: zero cross-block communication > last-block reduce (+2us tail)
//    > separate finalize launch (+5us);
//  - occupancy 43% vs 85%: neutral; warp segment 256B vs 512B: neutral;
//  - load scheduling: simple dependent-index loop + #pragma unroll 16
//    (ptxas-scheduled) optimum; manual register batching and two-chain
//    unroll-32 (regs 36, occ 71%, 5525 GB/s) both regress;
//  - __ldcs neutral; TMA offers no headroom (path-independent LTS cap);
//  - all-ones attention written in the epilogue of the same launch.
//
// Output layout (out_size = 98304 fp32):
//   [0      .. 32767 ]  context   (B=32, U=1024)
//   [32768  .. 98303 ]  attention (B=32, S=2048, 1) == 1.0f

#define BB 32
#define SS 2048
#define UU 1024
#define U4 (UU / 4)        // 256 float4 per row
#define NCHUNK 16          // U-chunks per batch row
#define C4 (U4 / NCHUNK)   // 16 float4 lanes per chunk
#define NT 512             // threads per block
#define SPHASE (NT / C4)   // 32 s-strides per block

__global__ void __launch_bounds__(NT) fused_kernel(const float4* __restrict__ hs,
                                                   float* __restrict__ out) {
    const int b = blockIdx.x;   // 0..31
    const int y = blockIdx.y;   // 0..15
    const int t = threadIdx.x;  // 0..511

    // ---- block (b, y): sum hs[b, :, y*64 : y*64+64] over all S ----
    const int lane = t & (C4 - 1);      // 0..15 -> float4 column in chunk
    const int srow = t >> 4;            // 0..31 -> starting s, stride 32

    const float4* __restrict__ base =
        hs + ((size_t)b * SS + srow) * U4 + y * C4 + lane;

    float4 acc = make_float4(0.f, 0.f, 0.f, 0.f);
#pragma unroll 16
    for (int s = 0; s < SS / SPHASE; ++s) {             // 64 iters, stride 32 rows
        float4 v = base[(size_t)s * SPHASE * U4];
        acc.x += v.x; acc.y += v.y; acc.z += v.z; acc.w += v.w;
    }

    // ---- deterministic in-block reduction of the 32 s-phases ----
    __shared__ float4 smem[NT];
    smem[t] = acc;
    __syncthreads();

    if (t < C4) {
        float4 r = make_float4(0.f, 0.f, 0.f, 0.f);
#pragma unroll
        for (int k = 0; k < SPHASE; ++k) {              // fixed order
            float4 v = smem[k * C4 + t];
            r.x += v.x; r.y += v.y; r.z += v.z; r.w += v.w;
        }
        ((float4*)out)[b * U4 + y * C4 + t] = r;
    }

    // ---- epilogue: attention region = 1.0, spread over all 512 blocks ----
    // 16384 float4 total / 512 blocks = 32 float4 per block (threads 32..63,
    // disjoint from the context-writing threads 0..15).
    if (t >= 32 && t < 64) {
        float4* ones = (float4*)(out + BB * UU);
        ones[(b * NCHUNK + y) * 32 + (t - 32)] = make_float4(1.f, 1.f, 1.f, 1.f);
    }
}

extern "C" void kernel_launch(void* const* d_in, const int* in_sizes, int n_in,
                              void* d_out, int out_size) {
    // Inputs: [0]=s_prev, [1]=hidden_states, [2]=Ww, [3]=Wb, [4]=Uw, [5]=Ub,
    //         [6]=Vw, [7]=Vb. Only hidden_states is live.
    const float4* hs = (const float4*)d_in[1];
    float* out = (float*)d_out;

    dim3 grid(BB, NCHUNK);
    fused_kernel<<<grid, NT>>>(hs, out);
}

// round 17
// speedup vs baseline: 1.0118x; 1.0118x over previous
#include <cuda_runtime.h>

// SelfAttention_61804579389661 — GB300 sm_103a — FINAL (converged, 5-run
// verified: bench 43.49-44.03us, kernel 42.62-44.00us, HBM 6194-6390 GB/s,
// rel_err 2.045896e-7 on every run)
//
// Algebraic simplification: softmax over a size-1 axis is identically 1.0,
// so attention == 1 and context[b,u] = sum_s hidden_states[b,s,u]. The
// entire tanh/GEMM pipeline in the reference is dead code; the problem is a
// pure 256 MiB read-reduce, bandwidth-bound (floor ~42.2us at the ~6.35
// TB/s empirical streaming cap; this kernel sits at ~99% of it).
//
// Fully-explored design grid (R1-R16), evidence per axis:
//  - decomposition: strided U-chunk (6.33-6.39 TB/s) > contiguous-per-block
//    (5.98-6.0 TB/s), at both high and low occupancy;
//  - fusion: zero cross-block communication > last-block reduce (+2us tail)
//    > separate finalize launch (+5us);
//  - occupancy 43% vs 85%: neutral; warp segment 256B vs 512B: neutral;
//  - load scheduling: simple dependent-index loop + #pragma unroll 16
//    (ptxas-scheduled) optimum; manual register batching and two-chain
//    unroll-32 (regs 36, occ 71%, 5525 GB/s) both regress;
//  - __ldcs neutral; TMA no headroom (path-independent LTS cap); persistent
//    grid void (all 512 CTAs co-resident -> no wave quantization);
//  - all-ones attention written in the epilogue of the same launch.
//
// Output layout (out_size = 98304 fp32):
//   [0      .. 32767 ]  context   (B=32, U=1024)
//   [32768  .. 98303 ]  attention (B=32, S=2048, 1) == 1.0f

#define BB 32
#define SS 2048
#define UU 1024
#define U4 (UU / 4)        // 256 float4 per row
#define NCHUNK 16          // U-chunks per batch row
#define C4 (U4 / NCHUNK)   // 16 float4 lanes per chunk
#define NT 512             // threads per block
#define SPHASE (NT / C4)   // 32 s-strides per block

__global__ void __launch_bounds__(NT) fused_kernel(const float4* __restrict__ hs,
                                                   float* __restrict__ out) {
    const int b = blockIdx.x;   // 0..31
    const int y = blockIdx.y;   // 0..15
    const int t = threadIdx.x;  // 0..511

    // ---- block (b, y): sum hs[b, :, y*64 : y*64+64] over all S ----
    const int lane = t & (C4 - 1);      // 0..15 -> float4 column in chunk
    const int srow = t >> 4;            // 0..31 -> starting s, stride 32

    const float4* __restrict__ base =
        hs + ((size_t)b * SS + srow) * U4 + y * C4 + lane;

    float4 acc = make_float4(0.f, 0.f, 0.f, 0.f);
#pragma unroll 16
    for (int s = 0; s < SS / SPHASE; ++s) {             // 64 iters, stride 32 rows
        float4 v = base[(size_t)s * SPHASE * U4];
        acc.x += v.x; acc.y += v.y; acc.z += v.z; acc.w += v.w;
    }

    // ---- deterministic in-block reduction of the 32 s-phases ----
    __shared__ float4 smem[NT];
    smem[t] = acc;
    __syncthreads();

    if (t < C4) {
        float4 r = make_float4(0.f, 0.f, 0.f, 0.f);
#pragma unroll
        for (int k = 0; k < SPHASE; ++k) {              // fixed order
            float4 v = smem[k * C4 + t];
            r.x += v.x; r.y += v.y; r.z += v.z; r.w += v.w;
        }
        ((float4*)out)[b * U4 + y * C4 + t] = r;
    }

    // ---- epilogue: attention region = 1.0, spread over all 512 blocks ----
    // 16384 float4 total / 512 blocks = 32 float4 per block (threads 32..63,
    // disjoint from the context-writing threads 0..15).
    if (t >= 32 && t < 64) {
        float4* ones = (float4*)(out + BB * UU);
        ones[(b * NCHUNK + y) * 32 + (t - 32)] = make_float4(1.f, 1.f, 1.f, 1.f);
    }
}

extern "C" void kernel_launch(void* const* d_in, const int* in_sizes, int n_in,
                              void* d_out, int out_size) {
    // Inputs: [0]=s_prev, [1]=hidden_states, [2]=Ww, [3]=Wb, [4]=Uw, [5]=Ub,
    //         [6]=Vw, [7]=Vb. Only hidden_states is live.
    const float4* hs = (const float4*)d_in[1];
    float* out = (float*)d_out;

    dim3 grid(BB, NCHUNK);
    fused_kernel<<<grid, NT>>>(hs, out);
}